// round 8
// baseline (speedup 1.0000x reference)
#include <cuda_runtime.h>
#include <float.h>

typedef unsigned long long U64;

// ---------------- scratch ----------------
#define D0_STRIDE 64012   // 64009 padded to mult of 4
#define D1_STRIDE 16132   // 16129 padded
__device__ float g_dist0[10 * D0_STRIDE];
__device__ float g_dist1[5 * D1_STRIDE];
__device__ float g_cand[360 * 5];
__device__ int   g_count;              // zero-init; self-reset each replay

// ---------------- packed f32x2 helpers ----------------
__device__ __forceinline__ U64 add2(U64 a, U64 b) {
    U64 r; asm("add.rn.f32x2 %0, %1, %2;" : "=l"(r) : "l"(a), "l"(b)); return r;
}
__device__ __forceinline__ U64 pack2(float lo, float hi) {
    U64 r; asm("mov.b64 %0, {%1, %2};" : "=l"(r) : "f"(lo), "f"(hi)); return r;
}
__device__ __forceinline__ float2 unpack2(U64 v) {
    float lo, hi; asm("mov.b64 {%0, %1}, %2;" : "=f"(lo), "=f"(hi) : "l"(v));
    return make_float2(lo, hi);
}
#define ABS2_MASK 0x7FFFFFFF7FFFFFFFULL

// =====================================================================
// dist kernel: round-2 inner loop, half-size CTAs for wave balance.
//   1-D grid of 576 CTAs x 128 threads, all active:
//   bx <  512 : scale0 (C=64,H=W=256,ps=3,Hm=253). tg=bx>>8 (5 targets),
//               spatial tile 32x8: tilex=(bx&255)&7, tiley=(bx&255)>>3
//   bx >= 512 : scale1 (C=128,H=W=128,ps=1,Hm=127), 2 pixels/thread
// =====================================================================
#define TILE_W 32
#define TILE_H 8
#define SM_W 34
#define SM_H 10
#define SM_N (SM_W * SM_H)   // 340
#define TPG 5

__global__ __launch_bounds__(128, 6) void dist_kernel(
    const float* __restrict__ src0, const float* __restrict__ tgt0,
    const int* __restrict__ pos0,
    const float* __restrict__ src1, const float* __restrict__ tgt1,
    const int* __restrict__ pos1)
{
    __shared__ U64 s_negt[32 * TPG * 10];        // padded [cp][T][10]
    __shared__ U64 s_tile[2][SM_N];              // double-buffered tile

    const int tid = threadIdx.x;
    const int bx  = blockIdx.x;

    // ---------------- scale-1 branch ----------------
    if (bx >= 512) {
        const int flat = bx - 512;               // 0..63
        U64* negt1 = s_negt;
        for (int i = tid; i < 64 * 5; i += 128) {
            int T = i % 5, cp = i / 5;
            int th = pos1[T * 2 + 0], tw = pos1[T * 2 + 1];
            const float* b = tgt1 + th * 128 + tw;
            negt1[i] = pack2(-b[(2 * cp) * 16384], -b[(2 * cp + 1) * 16384]);
        }
        __syncthreads();

        const int p0 = flat * 256 + tid;         // two pixels per thread
        const int p1 = p0 + 128;
        const int pc0 = p0 < 16129 ? p0 : 16128;
        const int pc1 = p1 < 16129 ? p1 : 16128;
        const int h0 = pc0 / 127, w0 = pc0 - h0 * 127;
        const int h1 = pc1 / 127, w1 = pc1 - h1 * 127;
        const float* sp0 = src1 + h0 * 128 + w0;
        const float* sp1 = src1 + h1 * 128 + w1;

        U64 accA[5], accB[5];
#pragma unroll
        for (int T = 0; T < 5; T++) { accA[T] = 0ULL; accB[T] = 0ULL; }

        for (int cp = 0; cp < 64; cp++) {
            U64 sA = pack2(sp0[(2 * cp) * 16384], sp0[(2 * cp + 1) * 16384]);
            U64 sB = pack2(sp1[(2 * cp) * 16384], sp1[(2 * cp + 1) * 16384]);
#pragma unroll
            for (int T = 0; T < 5; T++) {
                U64 nt = negt1[cp * 5 + T];
                U64 dA = add2(sA, nt) & ABS2_MASK;
                U64 dB = add2(sB, nt) & ABS2_MASK;
                accA[T] = add2(accA[T], dA);
                accB[T] = add2(accB[T], dB);
            }
        }
#pragma unroll
        for (int T = 0; T < 5; T++) {
            float2 a = unpack2(accA[T]);
            float2 b = unpack2(accB[T]);
            if (p0 < 16129) g_dist1[T * D1_STRIDE + p0] = a.x + a.y;
            if (p1 < 16129) g_dist1[T * D1_STRIDE + p1] = b.x + b.y;
        }
        return;
    }

    // ---------------- scale-0 branch ----------------
    const int sidx = bx & 255;
    const int tx = (sidx & 7) * TILE_W;
    const int ty = (sidx >> 3) * TILE_H;
    const int tb = (bx >> 8) * TPG;

    for (int i = tid; i < 32 * TPG * 9; i += 128) {
        int o  = i % 9;
        int T  = (i / 9) % TPG;
        int cp = i / (9 * TPG);
        int th = pos0[(tb + T) * 2 + 0];
        int tw = pos0[(tb + T) * 2 + 1];
        int di = o / 3, dj = o % 3;
        const float* b = tgt0 + (th + di) * 256 + (tw + dj);
        s_negt[cp * (TPG * 10) + T * 10 + o] =
            pack2(-b[(2 * cp) * 65536], -b[(2 * cp + 1) * 65536]);
    }

    int  goff[3];
    bool gval[3];
#pragma unroll
    for (int k = 0; k < 3; k++) {
        int i = tid + k * 128;
        int r = i / SM_W, c = i - r * SM_W;
        int y = ty + r, x = tx + c;
        gval[k] = (i < SM_N) && (y < 256) && (x < 256);
        goff[k] = y * 256 + x;
    }

    U64 pre[3];
    {   // prologue: cp = 0 -> buf 0
#pragma unroll
        for (int k = 0; k < 3; k++)
            pre[k] = gval[k] ? pack2(src0[goff[k]], src0[goff[k] + 65536]) : 0ULL;
#pragma unroll
        for (int k = 0; k < 3; k++) {
            int i = tid + k * 128;
            if (i < SM_N) s_tile[0][i] = pre[k];
        }
    }
    __syncthreads();

    const int thx = tid & 31;
    const int thy = tid >> 5;                  // 0..3
    const int w  = tx + thx;
    const int h0 = ty + 2 * thy;
    const bool act0 = (w < 253) && (h0 < 253);
    const bool act1 = (w < 253) && (h0 + 1 < 253);
    const int r0 = 2 * thy;

    U64 acc0[TPG], acc1[TPG];
#pragma unroll
    for (int T = 0; T < TPG; T++) { acc0[T] = 0ULL; acc1[T] = 0ULL; }

    for (int cp = 0; cp < 32; cp++) {
        if (cp + 1 < 32) {
            const float* s = src0 + (2 * (cp + 1)) * 65536;
#pragma unroll
            for (int k = 0; k < 3; k++)
                pre[k] = gval[k] ? pack2(s[goff[k]], s[goff[k] + 65536]) : 0ULL;
        }

        const U64* buf = s_tile[cp & 1];
        U64 sv[4][3];
#pragma unroll
        for (int r = 0; r < 4; r++)
#pragma unroll
            for (int j = 0; j < 3; j++)
                sv[r][j] = buf[(r0 + r) * SM_W + thx + j];

        const U64* tp = s_negt + cp * (TPG * 10);
#pragma unroll
        for (int T = 0; T < TPG; T++) {
            const ulonglong2* tp2 = (const ulonglong2*)(tp + T * 10);
#pragma unroll
            for (int o2 = 0; o2 < 4; o2++) {
                ulonglong2 q = tp2[o2];
                {
                    const int o = 2 * o2, di = o / 3, dj = o % 3;
                    U64 d0 = add2(sv[di][dj],     q.x) & ABS2_MASK;
                    U64 d1 = add2(sv[di + 1][dj], q.x) & ABS2_MASK;
                    acc0[T] = add2(acc0[T], d0);
                    acc1[T] = add2(acc1[T], d1);
                }
                {
                    const int o = 2 * o2 + 1, di = o / 3, dj = o % 3;
                    U64 d0 = add2(sv[di][dj],     q.y) & ABS2_MASK;
                    U64 d1 = add2(sv[di + 1][dj], q.y) & ABS2_MASK;
                    acc0[T] = add2(acc0[T], d0);
                    acc1[T] = add2(acc1[T], d1);
                }
            }
            {   // o = 8
                U64 nt = tp[T * 10 + 8];
                U64 d0 = add2(sv[2][2], nt) & ABS2_MASK;
                U64 d1 = add2(sv[3][2], nt) & ABS2_MASK;
                acc0[T] = add2(acc0[T], d0);
                acc1[T] = add2(acc1[T], d1);
            }
        }

        if (cp + 1 < 32) {
            U64* nb = s_tile[(cp + 1) & 1];
#pragma unroll
            for (int k = 0; k < 3; k++) {
                int i = tid + k * 128;
                if (i < SM_N) nb[i] = pre[k];
            }
            __syncthreads();
        }
    }

#pragma unroll
    for (int T = 0; T < TPG; T++) {
        float2 a0 = unpack2(acc0[T]);
        float2 a1 = unpack2(acc1[T]);
        if (act0) g_dist0[(tb + T) * D0_STRIDE + h0 * 253 + w]       = a0.x + a0.y;
        if (act1) g_dist0[(tb + T) * D0_STRIDE + (h0 + 1) * 253 + w] = a1.x + a1.y;
    }
}

// =====================================================================
// topk: 360 CTAs x 256. bx<320: t=bx/32, 32 chunks over dist0.
// bx>=320: t=10+(bx-320)/8, 8 chunks over dist1. Per-CTA top5 ->
// g_cand[bx*5]. Last CTA merges and writes scalar.
// =====================================================================
__device__ __forceinline__ void ins5(float& a0, float& a1, float& a2, float& a3,
                                     float& a4, float v)
{
    if (v < a4) {
        a4 = v; float t;
        if (a4 < a3) { t = a3; a3 = a4; a4 = t; }
        if (a3 < a2) { t = a2; a2 = a3; a3 = t; }
        if (a2 < a1) { t = a1; a1 = a2; a2 = t; }
        if (a1 < a0) { t = a0; a0 = a1; a1 = t; }
    }
}

__device__ __forceinline__ void warpTop5(float& a0, float& a1, float& a2,
                                         float& a3, float& a4)
{
#pragma unroll
    for (int m = 16; m >= 1; m >>= 1) {
        float b0 = __shfl_xor_sync(0xffffffffu, a0, m);
        float b1 = __shfl_xor_sync(0xffffffffu, a1, m);
        float b2 = __shfl_xor_sync(0xffffffffu, a2, m);
        float b3 = __shfl_xor_sync(0xffffffffu, a3, m);
        float b4 = __shfl_xor_sync(0xffffffffu, a4, m);
        ins5(a0, a1, a2, a3, a4, b0);
        ins5(a0, a1, a2, a3, a4, b1);
        ins5(a0, a1, a2, a3, a4, b2);
        ins5(a0, a1, a2, a3, a4, b3);
        ins5(a0, a1, a2, a3, a4, b4);
    }
}

#define NCTA_TOPK 360

__global__ __launch_bounds__(256) void topk_kernel(float* __restrict__ out)
{
    __shared__ float s_warp[8 * 5];
    __shared__ float s_partial[15];
    __shared__ int   s_last;

    const int bx   = blockIdx.x;
    const int tid  = threadIdx.x;
    const int wid  = tid >> 5;
    const int lane = tid & 31;

    const float* d;
    int n, nchunks, chunk;
    if (bx < 320) { chunk = bx & 31; nchunks = 32;
                    d = g_dist0 + (bx >> 5) * D0_STRIDE; n = 64009; }
    else          { chunk = (bx - 320) & 7; nchunks = 8;
                    d = g_dist1 + ((bx - 320) >> 3) * D1_STRIDE; n = 16129; }

    const int n4  = n >> 2;
    const int gpc = (n4 + nchunks - 1) / nchunks;
    const int g0  = chunk * gpc;
    const int g1  = min(n4, g0 + gpc);
    const float4* d4 = (const float4*)d;

    float a0 = FLT_MAX, a1 = FLT_MAX, a2 = FLT_MAX, a3 = FLT_MAX, a4 = FLT_MAX;
    for (int i = g0 + tid; i < g1; i += 256) {
        float4 v = d4[i];
        ins5(a0, a1, a2, a3, a4, v.x);
        ins5(a0, a1, a2, a3, a4, v.y);
        ins5(a0, a1, a2, a3, a4, v.z);
        ins5(a0, a1, a2, a3, a4, v.w);
    }
    if (chunk == 0 && tid == 0)                      // tail (n % 4 == 1)
        for (int i = n4 * 4; i < n; i++) ins5(a0, a1, a2, a3, a4, d[i]);

    warpTop5(a0, a1, a2, a3, a4);
    if (lane < 5) {
        float v = (lane == 0) ? a0 : (lane == 1) ? a1 : (lane == 2) ? a2
                 : (lane == 3) ? a3 : a4;
        s_warp[wid * 5 + lane] = v;
    }
    __syncthreads();
    if (wid == 0) {
        float b0 = (lane < 40) ? s_warp[lane] : FLT_MAX;
        a0 = b0; a1 = FLT_MAX; a2 = FLT_MAX; a3 = FLT_MAX; a4 = FLT_MAX;
        float b1 = (lane + 32 < 40) ? s_warp[lane + 32] : FLT_MAX;
        ins5(a0, a1, a2, a3, a4, b1);
        warpTop5(a0, a1, a2, a3, a4);
        if (lane == 0) {
            float* c = g_cand + bx * 5;
            c[0] = a0; c[1] = a1; c[2] = a2; c[3] = a3; c[4] = a4;
        }
    }

    // ---------------- last-CTA merge ----------------
    if (tid == 0) {
        __threadfence();
        int old = atomicAdd(&g_count, 1);
        s_last = (old == NCTA_TOPK - 1);
        if (s_last) g_count = 0;                    // reset for next replay
    }
    __syncthreads();
    if (!s_last) return;
    __threadfence();

    // warp w handles targets w and w+8
    for (int t = wid; t < 15; t += 8) {
        const float* c; int n2; float scale;
        if (t < 10) { c = g_cand + t * 160;              n2 = 160; scale = 1.0f / 28800.0f; }
        else        { c = g_cand + 1600 + (t - 10) * 40; n2 = 40;  scale = 1.0f / 6400.0f; }

        float m0 = FLT_MAX, m1 = FLT_MAX, m2 = FLT_MAX, m3 = FLT_MAX, m4 = FLT_MAX;
        for (int i = lane; i < n2; i += 32)
            ins5(m0, m1, m2, m3, m4, __ldcg(c + i));
        warpTop5(m0, m1, m2, m3, m4);
        if (lane == 0)
            s_partial[t] = (m0 + m1 + m2 + m3 + m4) * scale;
    }
    __syncthreads();
    if (tid == 0) {
        float s = 0.f;
#pragma unroll
        for (int i = 0; i < 15; i++) s += s_partial[i];
        out[0] = s;
    }
}

// =====================================================================
extern "C" void kernel_launch(void* const* d_in, const int* in_sizes, int n_in,
                              void* d_out, int out_size)
{
    const float* src0 = (const float*)d_in[0];
    const float* tgt0 = (const float*)d_in[1];
    const float* src1 = (const float*)d_in[2];
    const float* tgt1 = (const float*)d_in[3];
    const int*   pos0 = (const int*)d_in[4];
    const int*   pos1 = (const int*)d_in[5];

    dist_kernel<<<576, 128>>>(src0, tgt0, pos0, src1, tgt1, pos1);
    topk_kernel<<<NCTA_TOPK, 256>>>((float*)d_out);
}

// round 11
// speedup vs baseline: 1.0030x; 1.0030x over previous
#include <cuda_runtime.h>
#include <float.h>

typedef unsigned long long U64;

// ---------------- scratch ----------------
__device__ float g_cand0[10 * 256 * 4 * 5];   // [target][tile][warp][5]
__device__ float g_cand1[5 * 64 * 4 * 5];     // [target][CTA][warp][5]
__device__ float g_partial[16];
__device__ int   g_count;                     // zero-init; self-reset each replay

// ---------------- packed f32x2 helpers ----------------
__device__ __forceinline__ U64 add2(U64 a, U64 b) {
    U64 r; asm("add.rn.f32x2 %0, %1, %2;" : "=l"(r) : "l"(a), "l"(b)); return r;
}
__device__ __forceinline__ U64 pack2(float lo, float hi) {
    U64 r; asm("mov.b64 %0, {%1, %2};" : "=l"(r) : "f"(lo), "f"(hi)); return r;
}
__device__ __forceinline__ float2 unpack2(U64 v) {
    float lo, hi; asm("mov.b64 {%0, %1}, %2;" : "=f"(lo), "=f"(hi) : "l"(v));
    return make_float2(lo, hi);
}
#define ABS2_MASK 0x7FFFFFFF7FFFFFFFULL

// ---------------- sorted-5 insert + warp butterfly top-5 ----------------
__device__ __forceinline__ void ins5(float& a0, float& a1, float& a2, float& a3,
                                     float& a4, float v)
{
    if (v < a4) {
        a4 = v; float t;
        if (a4 < a3) { t = a3; a3 = a4; a4 = t; }
        if (a3 < a2) { t = a2; a2 = a3; a3 = t; }
        if (a2 < a1) { t = a1; a1 = a2; a2 = t; }
        if (a1 < a0) { t = a0; a0 = a1; a1 = t; }
    }
}

__device__ __forceinline__ void warpTop5(float& a0, float& a1, float& a2,
                                         float& a3, float& a4)
{
#pragma unroll
    for (int m = 16; m >= 1; m >>= 1) {
        float b0 = __shfl_xor_sync(0xffffffffu, a0, m);
        float b1 = __shfl_xor_sync(0xffffffffu, a1, m);
        float b2 = __shfl_xor_sync(0xffffffffu, a2, m);
        float b3 = __shfl_xor_sync(0xffffffffu, a3, m);
        float b4 = __shfl_xor_sync(0xffffffffu, a4, m);
        ins5(a0, a1, a2, a3, a4, b0);
        ins5(a0, a1, a2, a3, a4, b1);
        ins5(a0, a1, a2, a3, a4, b2);
        ins5(a0, a1, a2, a3, a4, b3);
        ins5(a0, a1, a2, a3, a4, b4);
    }
}

// =====================================================================
// dist kernel: round-2 inner loop (issue-floor core), 128-thread CTAs,
// per-warp top-5 epilogue (no dist maps).
//   1-D grid of 576 CTAs, all active:
//   bx <  512 : scale0. tg=bx>>8 (5 targets each), 32x8 spatial tile
//   bx >= 512 : scale1, 2 pixels/thread
// =====================================================================
#define TILE_W 32
#define TILE_H 8
#define SM_W 34
#define SM_H 10
#define SM_N (SM_W * SM_H)   // 340
#define TPG 5

__global__ __launch_bounds__(128, 6) void dist_kernel(
    const float* __restrict__ src0, const float* __restrict__ tgt0,
    const int* __restrict__ pos0,
    const float* __restrict__ src1, const float* __restrict__ tgt1,
    const int* __restrict__ pos1)
{
    __shared__ U64 s_negt[32 * TPG * 10];        // padded [cp][T][10]
    __shared__ U64 s_tile[2][SM_N];              // double-buffered tile

    const int tid  = threadIdx.x;
    const int bx   = blockIdx.x;
    const int wid  = tid >> 5;
    const int lane = tid & 31;

    // ---------------- scale-1 branch ----------------
    if (bx >= 512) {
        const int flat = bx - 512;               // 0..63
        U64* negt1 = s_negt;
        for (int i = tid; i < 64 * 5; i += 128) {
            int T = i % 5, cp = i / 5;
            int th = pos1[T * 2 + 0], tw = pos1[T * 2 + 1];
            const float* b = tgt1 + th * 128 + tw;
            negt1[i] = pack2(-b[(2 * cp) * 16384], -b[(2 * cp + 1) * 16384]);
        }
        __syncthreads();

        const int p0 = flat * 256 + tid;         // two pixels per thread
        const int p1 = p0 + 128;
        const int pc0 = p0 < 16129 ? p0 : 16128;
        const int pc1 = p1 < 16129 ? p1 : 16128;
        const int h0 = pc0 / 127, w0 = pc0 - h0 * 127;
        const int h1 = pc1 / 127, w1 = pc1 - h1 * 127;
        const float* sp0 = src1 + h0 * 128 + w0;
        const float* sp1 = src1 + h1 * 128 + w1;

        U64 accA[5], accB[5];
#pragma unroll
        for (int T = 0; T < 5; T++) { accA[T] = 0ULL; accB[T] = 0ULL; }

        for (int cp = 0; cp < 64; cp++) {
            U64 sA = pack2(sp0[(2 * cp) * 16384], sp0[(2 * cp + 1) * 16384]);
            U64 sB = pack2(sp1[(2 * cp) * 16384], sp1[(2 * cp + 1) * 16384]);
#pragma unroll
            for (int T = 0; T < 5; T++) {
                U64 nt = negt1[cp * 5 + T];
                U64 dA = add2(sA, nt) & ABS2_MASK;
                U64 dB = add2(sB, nt) & ABS2_MASK;
                accA[T] = add2(accA[T], dA);
                accB[T] = add2(accB[T], dB);
            }
        }
#pragma unroll
        for (int T = 0; T < 5; T++) {
            float2 a = unpack2(accA[T]);
            float2 b = unpack2(accB[T]);
            float v0 = (p0 < 16129) ? (a.x + a.y) : FLT_MAX;
            float v1 = (p1 < 16129) ? (b.x + b.y) : FLT_MAX;
            float a0 = fminf(v0, v1), a1 = fmaxf(v0, v1);
            float a2 = FLT_MAX, a3 = FLT_MAX, a4 = FLT_MAX;
            warpTop5(a0, a1, a2, a3, a4);
            if (lane == 0) {
                float* c = g_cand1 + ((T * 64 + flat) * 4 + wid) * 5;
                c[0] = a0; c[1] = a1; c[2] = a2; c[3] = a3; c[4] = a4;
            }
        }
        return;
    }

    // ---------------- scale-0 branch ----------------
    const int sidx = bx & 255;
    const int tx = (sidx & 7) * TILE_W;
    const int ty = (sidx >> 3) * TILE_H;
    const int tb = (bx >> 8) * TPG;

    for (int i = tid; i < 32 * TPG * 9; i += 128) {
        int o  = i % 9;
        int T  = (i / 9) % TPG;
        int cp = i / (9 * TPG);
        int th = pos0[(tb + T) * 2 + 0];
        int tw = pos0[(tb + T) * 2 + 1];
        int di = o / 3, dj = o % 3;
        const float* b = tgt0 + (th + di) * 256 + (tw + dj);
        s_negt[cp * (TPG * 10) + T * 10 + o] =
            pack2(-b[(2 * cp) * 65536], -b[(2 * cp + 1) * 65536]);
    }

    int  goff[3];
    bool gval[3];
#pragma unroll
    for (int k = 0; k < 3; k++) {
        int i = tid + k * 128;
        int r = i / SM_W, c = i - r * SM_W;
        int y = ty + r, x = tx + c;
        gval[k] = (i < SM_N) && (y < 256) && (x < 256);
        goff[k] = y * 256 + x;
    }

    U64 pre[3];
    {   // prologue: cp = 0 -> buf 0
#pragma unroll
        for (int k = 0; k < 3; k++)
            pre[k] = gval[k] ? pack2(src0[goff[k]], src0[goff[k] + 65536]) : 0ULL;
#pragma unroll
        for (int k = 0; k < 3; k++) {
            int i = tid + k * 128;
            if (i < SM_N) s_tile[0][i] = pre[k];
        }
    }
    __syncthreads();

    const int thx = lane;
    const int w  = tx + thx;
    const int h0 = ty + 2 * wid;
    const bool act0 = (w < 253) && (h0 < 253);
    const bool act1 = (w < 253) && (h0 + 1 < 253);
    const int r0 = 2 * wid;

    U64 acc0[TPG], acc1[TPG];
#pragma unroll
    for (int T = 0; T < TPG; T++) { acc0[T] = 0ULL; acc1[T] = 0ULL; }

    for (int cp = 0; cp < 32; cp++) {
        if (cp + 1 < 32) {
            const float* s = src0 + (2 * (cp + 1)) * 65536;
#pragma unroll
            for (int k = 0; k < 3; k++)
                pre[k] = gval[k] ? pack2(s[goff[k]], s[goff[k] + 65536]) : 0ULL;
        }

        const U64* buf = s_tile[cp & 1];
        U64 sv[4][3];
#pragma unroll
        for (int r = 0; r < 4; r++)
#pragma unroll
            for (int j = 0; j < 3; j++)
                sv[r][j] = buf[(r0 + r) * SM_W + thx + j];

        const U64* tp = s_negt + cp * (TPG * 10);
#pragma unroll
        for (int T = 0; T < TPG; T++) {
            const ulonglong2* tp2 = (const ulonglong2*)(tp + T * 10);
#pragma unroll
            for (int o2 = 0; o2 < 4; o2++) {
                ulonglong2 q = tp2[o2];
                {
                    const int o = 2 * o2, di = o / 3, dj = o % 3;
                    U64 d0 = add2(sv[di][dj],     q.x) & ABS2_MASK;
                    U64 d1 = add2(sv[di + 1][dj], q.x) & ABS2_MASK;
                    acc0[T] = add2(acc0[T], d0);
                    acc1[T] = add2(acc1[T], d1);
                }
                {
                    const int o = 2 * o2 + 1, di = o / 3, dj = o % 3;
                    U64 d0 = add2(sv[di][dj],     q.y) & ABS2_MASK;
                    U64 d1 = add2(sv[di + 1][dj], q.y) & ABS2_MASK;
                    acc0[T] = add2(acc0[T], d0);
                    acc1[T] = add2(acc1[T], d1);
                }
            }
            {   // o = 8
                U64 nt = tp[T * 10 + 8];
                U64 d0 = add2(sv[2][2], nt) & ABS2_MASK;
                U64 d1 = add2(sv[3][2], nt) & ABS2_MASK;
                acc0[T] = add2(acc0[T], d0);
                acc1[T] = add2(acc1[T], d1);
            }
        }

        if (cp + 1 < 32) {
            U64* nb = s_tile[(cp + 1) & 1];
#pragma unroll
            for (int k = 0; k < 3; k++) {
                int i = tid + k * 128;
                if (i < SM_N) nb[i] = pre[k];
            }
            __syncthreads();
        }
    }

    // per-warp top-5 epilogue (values stay in registers; no dist maps)
#pragma unroll
    for (int T = 0; T < TPG; T++) {
        float2 A0 = unpack2(acc0[T]);
        float2 A1 = unpack2(acc1[T]);
        float v0 = act0 ? (A0.x + A0.y) : FLT_MAX;
        float v1 = act1 ? (A1.x + A1.y) : FLT_MAX;
        float a0 = fminf(v0, v1), a1 = fmaxf(v0, v1);
        float a2 = FLT_MAX, a3 = FLT_MAX, a4 = FLT_MAX;
        warpTop5(a0, a1, a2, a3, a4);
        if (lane == 0) {
            float* c = g_cand0 + (((tb + T) * 256 + sidx) * 4 + wid) * 5;
            c[0] = a0; c[1] = a1; c[2] = a2; c[3] = a3; c[4] = a4;
        }
    }
}

// =====================================================================
// merge: 15 CTAs x 256 threads. CTA t reduces its target's candidates
// (5120 floats for scale0, 1280 for scale1) to top-5; last CTA sums.
// =====================================================================
__global__ __launch_bounds__(256) void merge_kernel(float* __restrict__ out)
{
    __shared__ float s_warp[8 * 5];
    __shared__ int   s_last;

    const int t    = blockIdx.x;
    const int tid  = threadIdx.x;
    const int wid  = tid >> 5;
    const int lane = tid & 31;

    const float* d;
    int n; float scale;
    if (t < 10) { d = g_cand0 + t * 5120;        n = 5120; scale = 1.0f / 28800.0f; }
    else        { d = g_cand1 + (t - 10) * 1280; n = 1280; scale = 1.0f / 6400.0f; }

    const float4* d4 = (const float4*)d;         // n divisible by 4, 16B aligned
    float a0 = FLT_MAX, a1 = FLT_MAX, a2 = FLT_MAX, a3 = FLT_MAX, a4 = FLT_MAX;
    for (int i = tid; i < (n >> 2); i += 256) {
        float4 v = d4[i];
        ins5(a0, a1, a2, a3, a4, v.x);
        ins5(a0, a1, a2, a3, a4, v.y);
        ins5(a0, a1, a2, a3, a4, v.z);
        ins5(a0, a1, a2, a3, a4, v.w);
    }

    warpTop5(a0, a1, a2, a3, a4);
    if (lane < 5) {
        float v = (lane == 0) ? a0 : (lane == 1) ? a1 : (lane == 2) ? a2
                 : (lane == 3) ? a3 : a4;
        s_warp[wid * 5 + lane] = v;
    }
    __syncthreads();
    if (wid == 0) {
        a0 = (lane < 40) ? s_warp[lane] : FLT_MAX;
        a1 = FLT_MAX; a2 = FLT_MAX; a3 = FLT_MAX; a4 = FLT_MAX;
        float b1 = (lane + 32 < 40) ? s_warp[lane + 32] : FLT_MAX;
        ins5(a0, a1, a2, a3, a4, b1);
        warpTop5(a0, a1, a2, a3, a4);
        if (lane == 0)
            g_partial[t] = (a0 + a1 + a2 + a3 + a4) * scale;
    }

    // ---------------- last-CTA finalize ----------------
    if (tid == 0) {
        __threadfence();
        int old = atomicAdd(&g_count, 1);
        s_last = (old == 14);
        if (s_last) g_count = 0;                 // reset for next replay
    }
    __syncthreads();
    if (!s_last) return;
    if (tid == 0) {
        __threadfence();
        volatile float* gp = g_partial;
        float s = 0.f;
#pragma unroll
        for (int i = 0; i < 15; i++) s += gp[i]; // fixed order: deterministic
        out[0] = s;
    }
}

// =====================================================================
extern "C" void kernel_launch(void* const* d_in, const int* in_sizes, int n_in,
                              void* d_out, int out_size)
{
    const float* src0 = (const float*)d_in[0];
    const float* tgt0 = (const float*)d_in[1];
    const float* src1 = (const float*)d_in[2];
    const float* tgt1 = (const float*)d_in[3];
    const int*   pos0 = (const int*)d_in[4];
    const int*   pos1 = (const int*)d_in[5];

    dist_kernel<<<576, 128>>>(src0, tgt0, pos0, src1, tgt1, pos1);
    merge_kernel<<<15, 256>>>((float*)d_out);
}